// round 2
// baseline (speedup 1.0000x reference)
#include <cuda_runtime.h>

#define TT 512
#define BB 128
#define EE 128
#define SS 1024
#define LOG2T 10

// ---- b-major tables (consumed by k_gemm, staged to smem per block) ----
__device__ float g_h[BB][TT + 1];      // g_h[b][0]=0, g_h[b][t+1]=h_t
__device__ float g_e[BB][TT];          // e[tau] = h_{tau-1} - d1_tau
__device__ float g_gtop[BB][TT];       // h_t - u_t
__device__ float g_st[BB][LOG2T][TT];  // sparse table over h
// ---- t-major (b fastest) tables (consumed by k_m, coalesced) ----
__device__ float g_h_tm[TT + 1][BB];
__device__ float g_e_tm[TT][BB];
__device__ float g_gtop_tm[TT][BB];
__device__ float g_st_tm[LOG2T][TT][BB];
// ---- batch-max per (t, slot) ----
__device__ float g_m[TT][SS];

// ---------------------------------------------------------------------------
// K1: per-batch fp64 prefix sums + sparse table. One block per batch.
// ---------------------------------------------------------------------------
__global__ void k_prep(const float* __restrict__ d1,
                       const float* __restrict__ d2,
                       const float* __restrict__ uu_) {
    int b = blockIdx.x;
    int t = threadIdx.x;  // 512 threads

    float d1v = d1[t * BB + b];
    float d2v = d2[t * BB + b];
    float uv  = uu_[t * BB + b];
    double P = (double)d1v + (double)d2v;
    double U = (double)uv;

    __shared__ double sP[16], sU[16];
    int lane = t & 31, warp = t >> 5;
    double pi = P, ui = U;
    #pragma unroll
    for (int o = 1; o < 32; o <<= 1) {
        double a = __shfl_up_sync(0xffffffffu, pi, o);
        double c = __shfl_up_sync(0xffffffffu, ui, o);
        if (lane >= o) { pi += a; ui += c; }
    }
    if (lane == 31) { sP[warp] = pi; sU[warp] = ui; }
    __syncthreads();
    if (warp == 0) {
        double pw = (lane < 16) ? sP[lane] : 0.0;
        double uw = (lane < 16) ? sU[lane] : 0.0;
        #pragma unroll
        for (int o = 1; o < 16; o <<= 1) {
            double a = __shfl_up_sync(0xffffffffu, pw, o);
            double c = __shfl_up_sync(0xffffffffu, uw, o);
            if (lane >= o) { pw += a; uw += c; }
        }
        if (lane < 16) { sP[lane] = pw; sU[lane] = uw; }
    }
    __syncthreads();
    double PP = pi + (warp ? sP[warp - 1] : 0.0);
    double UU = ui + (warp ? sU[warp - 1] : 0.0);

    float h    = (float)(UU - PP);
    float ev   = (float)((UU - U) - (PP - P) - (double)d1v);
    float gtop = (float)(UU - PP - (double)uv);

    g_h[b][t + 1]     = h;
    g_h_tm[t + 1][b]  = h;
    if (t == 0) { g_h[b][0] = 0.f; g_h_tm[0][b] = 0.f; }
    g_e[b][t]         = ev;
    g_e_tm[t][b]      = ev;
    g_gtop[b][t]      = gtop;
    g_gtop_tm[t][b]   = gtop;

    __shared__ float buf0[TT], buf1[TT];
    buf0[t] = h;
    g_st[b][0][t]    = h;
    g_st_tm[0][t][b] = h;
    __syncthreads();
    float* prev = buf0;
    float* cur  = buf1;
    for (int k = 1; k < LOG2T; k++) {
        int off = 1 << (k - 1);
        int j = t + off;
        if (j > TT - 1) j = TT - 1;
        float v = fmaxf(prev[t], prev[j]);
        cur[t] = v;
        g_st[b][k][t]    = v;
        g_st_tm[k][t][b] = v;
        __syncthreads();
        float* tmp = prev; prev = cur; cur = tmp;
    }
}

// ---------------------------------------------------------------------------
// K2: m[t][s] = max_b (u - used). Block per t, 128 threads (b = tid).
// All global loads coalesced via t-major tables; 1 barrier per 32 taus.
// ---------------------------------------------------------------------------
__global__ void k_m(void) {
    int t = blockIdx.x;
    int b = threadIdx.x;
    int lane = b & 31, w = b >> 5;
    float ht = g_h_tm[t + 1][b];

    __shared__ float part[4][64];

    for (int tau0 = 0; tau0 <= t; tau0 += 32) {
        int nt = t - tau0 + 1;
        if (nt > 32) nt = 32;
        for (int i = 0; i < nt; i++) {
            int tau = tau0 + i;
            float G;
            if (tau == t) {
                G = g_gtop_tm[t][b];
            } else {
                int len = t - tau;
                int k = 31 - __clz(len);
                G = fmaxf(g_st_tm[k][tau][b], g_st_tm[k][t - (1 << k)][b]);
            }
            float Bv = fmaxf(g_e_tm[tau][b], G);
            float v1 = ht - Bv;   // even slot 2*tau
            float v2 = ht - G;    // odd  slot 2*tau+1
            #pragma unroll
            for (int o = 16; o; o >>= 1) {
                v1 = fmaxf(v1, __shfl_xor_sync(0xffffffffu, v1, o));
                v2 = fmaxf(v2, __shfl_xor_sync(0xffffffffu, v2, o));
            }
            if (lane == 0) { part[w][2 * i] = v1; part[w][2 * i + 1] = v2; }
        }
        __syncthreads();
        if (b < 2 * nt) {
            float m = fmaxf(fmaxf(part[0][b], part[1][b]),
                            fmaxf(part[2][b], part[3][b]));
            g_m[t][2 * tau0 + b] = m;
        }
        __syncthreads();
    }
}

// ---------------------------------------------------------------------------
// K3 (fused): GEMM with on-the-fly W computation from smem tables.
// Block (c,b): rows t0..t0+127, K = 256*(c+1) slots. 256 threads, 8x8/thread
// in split 4+4 tiling (conflict-free LDS.128).
// ---------------------------------------------------------------------------
__global__ void __launch_bounds__(256, 2) k_gemm(const float* __restrict__ v1,
                                                 const float* __restrict__ v2,
                                                 float* __restrict__ out) {
    int c = blockIdx.x;   // 0..3
    int b = blockIdx.y;   // 0..127
    int t0 = c * 128;
    int K = 2 * (t0 + 128);

    __shared__ float st_s[LOG2T * TT];   // 20KB
    __shared__ float e_s[TT];
    __shared__ float h_s[TT];            // h_s[tau] = h_{tau-1}
    __shared__ float gtop_s[128];
    __shared__ float Ws[16][132];        // k-major W tile (padded)
    __shared__ float Vs[16][128];        // k-major V tile

    int tid = threadIdx.x;
    int tx = tid & 15;    // e-block
    int ty = tid >> 4;    // t-block

    // stage per-b tables
    {
        const float* src = &g_st[b][0][0];
        for (int i = tid; i < LOG2T * TT; i += 256) st_s[i] = src[i];
        for (int i = tid; i < TT; i += 256) { e_s[i] = g_e[b][i]; h_s[i] = g_h[b][i]; }
        if (tid < 128) gtop_s[tid] = g_gtop[b][t0 + tid];
    }
    __syncthreads();

    float acc[8][8];
    #pragma unroll
    for (int i = 0; i < 8; i++)
        #pragma unroll
        for (int j = 0; j < 8; j++) acc[i][j] = 0.f;

    for (int s0 = 0; s0 < K; s0 += 16) {
        // --- V tile load (coalesced) ---
        #pragma unroll
        for (int p = 0; p < 2; p++) {
            int sr = (tid >> 5) + p * 8;
            int s = s0 + sr;
            int tau = s >> 1;
            const float* src = (s & 1) ? v2 : v1;
            float4 vv = *(const float4*)(src + ((size_t)tau * BB + b) * EE + (tid & 31) * 4);
            *(float4*)&Vs[sr][(tid & 31) * 4] = vv;
        }
        // --- W tile eval (from smem tables) ---
        #pragma unroll
        for (int q = 0; q < 8; q++) {
            int id = tid + q * 256;
            int sc = id & 15, r = id >> 4;
            int s = s0 + sc, t = t0 + r;
            float w = 0.f;
            if (s <= 2 * t + 1) {
                int tau = s >> 1;
                float G;
                if (tau == t) {
                    G = gtop_s[r];
                } else {
                    int len = t - tau;
                    int k = 31 - __clz(len);
                    G = fmaxf(st_s[k * TT + tau], st_s[k * TT + t - (1 << k)]);
                }
                float Bv = fmaxf(e_s[tau], G);
                float stv = (s & 1) ? (Bv - G) : (fmaxf(h_s[tau], G) - Bv);
                w = fminf(stv, g_m[t][s]);
            }
            Ws[sc][r] = w;
        }
        __syncthreads();
        // --- FFMA ---
        #pragma unroll
        for (int k = 0; k < 16; k++) {
            float4 a0 = *(const float4*)&Ws[k][ty * 4];
            float4 a1 = *(const float4*)&Ws[k][64 + ty * 4];
            float4 b0 = *(const float4*)&Vs[k][tx * 4];
            float4 b1 = *(const float4*)&Vs[k][64 + tx * 4];
            float av[8] = {a0.x, a0.y, a0.z, a0.w, a1.x, a1.y, a1.z, a1.w};
            float bv[8] = {b0.x, b0.y, b0.z, b0.w, b1.x, b1.y, b1.z, b1.w};
            #pragma unroll
            for (int i = 0; i < 8; i++)
                #pragma unroll
                for (int j = 0; j < 8; j++)
                    acc[i][j] = fmaf(av[i], bv[j], acc[i][j]);
        }
        __syncthreads();
    }

    // --- store: rows {ty*4+i, 64+ty*4+i}, cols {tx*4+j, 64+tx*4+j} ---
    #pragma unroll
    for (int i = 0; i < 8; i++) {
        int row = (i < 4) ? (ty * 4 + i) : (64 + ty * 4 + (i - 4));
        int trow = t0 + row;
        float* orow = out + ((size_t)trow * BB + b) * EE;
        *(float4*)(orow + tx * 4)      = make_float4(acc[i][0], acc[i][1], acc[i][2], acc[i][3]);
        *(float4*)(orow + 64 + tx * 4) = make_float4(acc[i][4], acc[i][5], acc[i][6], acc[i][7]);
    }
}

extern "C" void kernel_launch(void* const* d_in, const int* in_sizes, int n_in,
                              void* d_out, int out_size) {
    const float* v1 = (const float*)d_in[0];
    const float* v2 = (const float*)d_in[1];
    const float* d1 = (const float*)d_in[2];
    const float* d2 = (const float*)d_in[3];
    const float* u  = (const float*)d_in[4];
    float* out = (float*)d_out;

    k_prep<<<BB, TT>>>(d1, d2, u);
    k_m<<<TT, BB>>>();
    k_gemm<<<dim3(4, BB), 256>>>(v1, v2, out);
}

// round 4
// speedup vs baseline: 3.6974x; 3.6974x over previous
#include <cuda_runtime.h>
#include <cuda_fp16.h>
#include <cstdint>

#define TT 512
#define BB 128
#define EE 128
#define SS 1024
#define LOG2T 10

// ---- tables ----
__device__ float g_h[BB][TT + 1];      // g_h[b][0]=0, g_h[b][t+1]=h_t
__device__ float g_e[BB][TT];          // e[tau] = h_{tau-1} - d1_tau
__device__ float g_gtop[BB][TT];       // h_t - u_t
__device__ float g_st[BB][LOG2T][TT];  // sparse table over h (b-major)
__device__ float g_h_tm[TT + 1][BB];   // t-major copies for k_m
__device__ float g_e_tm[TT][BB];
__device__ float g_gtop_tm[TT][BB];
__device__ float g_st_tm[LOG2T][TT][BB];
__device__ float g_m[TT][SS];          // batch-max per (t, slot)
__device__ __half g_wh[BB][TT][SS];    // W as fp16
__device__ __half g_vt[BB][EE][SS];    // V^T as fp16

// ---------------------------------------------------------------------------
// helpers
// ---------------------------------------------------------------------------
__device__ __forceinline__ uint32_t su32(const void* p) {
    uint32_t a;
    asm("{ .reg .u64 t; cvta.to.shared.u64 t, %1; cvt.u32.u64 %0, t; }"
        : "=r"(a) : "l"(p));
    return a;
}
__device__ __forceinline__ void ldm_x4(uint32_t* r, uint32_t addr) {
    asm volatile("ldmatrix.sync.aligned.m8n8.x4.shared.b16 {%0,%1,%2,%3}, [%4];"
                 : "=r"(r[0]), "=r"(r[1]), "=r"(r[2]), "=r"(r[3]) : "r"(addr));
}
__device__ __forceinline__ void mma16816(float* d, const uint32_t* a,
                                         uint32_t b0, uint32_t b1) {
    asm volatile(
        "mma.sync.aligned.m16n8k16.row.col.f32.f16.f16.f32 "
        "{%0,%1,%2,%3}, {%4,%5,%6,%7}, {%8,%9}, {%0,%1,%2,%3};"
        : "+f"(d[0]), "+f"(d[1]), "+f"(d[2]), "+f"(d[3])
        : "r"(a[0]), "r"(a[1]), "r"(a[2]), "r"(a[3]), "r"(b0), "r"(b1));
}

// ---------------------------------------------------------------------------
// K1: per-batch fp64 prefix sums + sparse table. One block per batch.
// ---------------------------------------------------------------------------
__global__ void k_prep(const float* __restrict__ d1,
                       const float* __restrict__ d2,
                       const float* __restrict__ uu_) {
    int b = blockIdx.x;
    int t = threadIdx.x;  // 512 threads

    float d1v = d1[t * BB + b];
    float d2v = d2[t * BB + b];
    float uv  = uu_[t * BB + b];
    double P = (double)d1v + (double)d2v;
    double U = (double)uv;

    __shared__ double sP[16], sU[16];
    int lane = t & 31, warp = t >> 5;
    double pi = P, ui = U;
    #pragma unroll
    for (int o = 1; o < 32; o <<= 1) {
        double a = __shfl_up_sync(0xffffffffu, pi, o);
        double c = __shfl_up_sync(0xffffffffu, ui, o);
        if (lane >= o) { pi += a; ui += c; }
    }
    if (lane == 31) { sP[warp] = pi; sU[warp] = ui; }
    __syncthreads();
    if (warp == 0) {
        double pw = (lane < 16) ? sP[lane] : 0.0;
        double uw = (lane < 16) ? sU[lane] : 0.0;
        #pragma unroll
        for (int o = 1; o < 16; o <<= 1) {
            double a = __shfl_up_sync(0xffffffffu, pw, o);
            double c = __shfl_up_sync(0xffffffffu, uw, o);
            if (lane >= o) { pw += a; uw += c; }
        }
        if (lane < 16) { sP[lane] = pw; sU[lane] = uw; }
    }
    __syncthreads();
    double PP = pi + (warp ? sP[warp - 1] : 0.0);
    double UU = ui + (warp ? sU[warp - 1] : 0.0);

    float h    = (float)(UU - PP);
    float ev   = (float)((UU - U) - (PP - P) - (double)d1v);
    float gtop = (float)(UU - PP - (double)uv);

    g_h[b][t + 1]    = h;
    g_h_tm[t + 1][b] = h;
    if (t == 0) { g_h[b][0] = 0.f; g_h_tm[0][b] = 0.f; }
    g_e[b][t]       = ev;
    g_e_tm[t][b]    = ev;
    g_gtop[b][t]    = gtop;
    g_gtop_tm[t][b] = gtop;

    __shared__ float buf0[TT], buf1[TT];
    buf0[t] = h;
    g_st[b][0][t]    = h;
    g_st_tm[0][t][b] = h;
    __syncthreads();
    float* prev = buf0;
    float* cur  = buf1;
    for (int k = 1; k < LOG2T; k++) {
        int off = 1 << (k - 1);
        int j = t + off;
        if (j > TT - 1) j = TT - 1;
        float v = fmaxf(prev[t], prev[j]);
        cur[t] = v;
        g_st[b][k][t]    = v;
        g_st_tm[k][t][b] = v;
        __syncthreads();
        float* tmp = prev; prev = cur; cur = tmp;
    }
}

// ---------------------------------------------------------------------------
// K2: m[t][s] = max_b (u - used). grid (TT, 16), 128 threads (b = tid).
// ---------------------------------------------------------------------------
__global__ void k_m(void) {
    int t = blockIdx.x;
    int tau0 = blockIdx.y * 32;
    if (tau0 > t) return;
    int b = threadIdx.x;
    int lane = b & 31, w = b >> 5;
    float ht = g_h_tm[t + 1][b];

    __shared__ float part[4][64];

    int nt = t - tau0 + 1;
    if (nt > 32) nt = 32;
    for (int i = 0; i < nt; i++) {
        int tau = tau0 + i;
        float G;
        if (tau == t) {
            G = g_gtop_tm[t][b];
        } else {
            int len = t - tau;
            int k = 31 - __clz(len);
            G = fmaxf(g_st_tm[k][tau][b], g_st_tm[k][t - (1 << k)][b]);
        }
        float Bv = fmaxf(g_e_tm[tau][b], G);
        float v1 = ht - Bv;
        float v2 = ht - G;
        #pragma unroll
        for (int o = 16; o; o >>= 1) {
            v1 = fmaxf(v1, __shfl_xor_sync(0xffffffffu, v1, o));
            v2 = fmaxf(v2, __shfl_xor_sync(0xffffffffu, v2, o));
        }
        if (lane == 0) { part[w][2 * i] = v1; part[w][2 * i + 1] = v2; }
    }
    __syncthreads();
    if (b < 2 * nt) {
        float m = fmaxf(fmaxf(part[0][b], part[1][b]),
                        fmaxf(part[2][b], part[3][b]));
        g_m[t][2 * tau0 + b] = m;
    }
}

// ---------------------------------------------------------------------------
// K3: W -> g_wh fp16. Block = (t-chunk of 32, b); tables staged in smem.
// ---------------------------------------------------------------------------
__global__ void __launch_bounds__(256) k_w(void) {
    int tb = blockIdx.x * 32;
    int b  = blockIdx.y;
    int tid = threadIdx.x;

    __shared__ float st_s[LOG2T * TT];
    __shared__ float e_s[TT];
    __shared__ float h_s[TT];
    __shared__ float gt_s[32];

    const float* src = &g_st[b][0][0];
    for (int i = tid; i < LOG2T * TT; i += 256) st_s[i] = src[i];
    for (int i = tid; i < TT; i += 256) { e_s[i] = g_e[b][i]; h_s[i] = g_h[b][i]; }
    if (tid < 32) gt_s[tid] = g_gtop[b][tb + tid];
    __syncthreads();

    int s0 = (tid & 127) * 8;
    for (int tt = 0; tt < 16; tt++) {
        int r = tt * 2 + (tid >> 7);
        int t = tb + r;
        int s_end = ((t >> 7) + 1) << 8;
        if (s0 >= s_end) continue;

        float4 m0 = *(const float4*)&g_m[t][s0];
        float4 m1 = *(const float4*)&g_m[t][s0 + 4];
        float mv[8] = {m0.x, m0.y, m0.z, m0.w, m1.x, m1.y, m1.z, m1.w};

        __align__(16) __half wv[8];
        #pragma unroll
        for (int jj = 0; jj < 4; jj++) {
            int tau = (s0 >> 1) + jj;
            float we = 0.f, wo = 0.f;
            if (tau <= t) {
                float G;
                if (tau == t) {
                    G = gt_s[r];
                } else {
                    int len = t - tau;
                    int k = 31 - __clz(len);
                    G = fmaxf(st_s[k * TT + tau], st_s[k * TT + t - (1 << k)]);
                }
                float Bv = fmaxf(e_s[tau], G);
                we = fminf(fmaxf(h_s[tau], G) - Bv, mv[2 * jj]);
                wo = fminf(Bv - G, mv[2 * jj + 1]);
            }
            wv[2 * jj]     = __float2half(we);
            wv[2 * jj + 1] = __float2half(wo);
        }
        *(uint4*)&g_wh[b][t][s0] = *(const uint4*)wv;
    }
}

// ---------------------------------------------------------------------------
// K4: transpose+convert V -> g_vt[b][e][s] fp16. Block = (s-chunk 64, b).
// ---------------------------------------------------------------------------
__global__ void __launch_bounds__(256) k_vt(const float* __restrict__ v1,
                                            const float* __restrict__ v2) {
    int sc = blockIdx.x;      // 0..15
    int b  = blockIdx.y;
    int tid = threadIdx.x;
    int tau0 = sc * 32;

    __shared__ __half sv[64][130];

    for (int u = tid; u < 4096; u += 256) {
        int i = u >> 7, e = u & 127;
        size_t gi = ((size_t)(tau0 + i) * BB + b) * EE + e;
        sv[2 * i][e]     = __float2half(v1[gi]);
        sv[2 * i + 1][e] = __float2half(v2[gi]);
    }
    __syncthreads();

    int e = tid >> 1, sh = (tid & 1) * 32;
    __align__(16) __half hb[32];
    #pragma unroll
    for (int j = 0; j < 32; j++) hb[j] = sv[sh + j][e];
    uint4* gout = (uint4*)&g_vt[b][e][sc * 64 + sh];
    const uint4* hb4 = (const uint4*)hb;
    gout[0] = hb4[0]; gout[1] = hb4[1]; gout[2] = hb4[2]; gout[3] = hb4[3];
}

// ---------------------------------------------------------------------------
// K5: mma.sync fp16 GEMM. Block (c,b): D[128t x 128e] = W[128 x K] @ Vt^T.
// K chunks of 64. 8 warps = 4(m) x 2(n), warp tile 32x64.
// ---------------------------------------------------------------------------
#define LDS_STRIDE 72  // halfs per row (144B) — conflict-free ldmatrix

__global__ void __launch_bounds__(256) k_gemm(float* __restrict__ out) {
    int c = blockIdx.x;   // 0..3
    int b = blockIdx.y;   // 0..127
    int t0 = c * 128;
    int K = 2 * (t0 + 128);

    __shared__ __half As[128 * LDS_STRIDE];
    __shared__ __half Bs[128 * LDS_STRIDE];

    int tid = threadIdx.x;
    int wid = tid >> 5, lane = tid & 31;
    int wm = wid >> 1, wn = wid & 1;

    uint32_t as_base = su32(As);
    uint32_t bs_base = su32(Bs);

    // ldmatrix source addresses (k-step column added per step)
    int a_row = wm * 32 + (lane & 15);
    int a_col = (lane >> 4) * 8;
    int b_row = wn * 64 + (lane >> 4) * 8 + (lane & 7);
    int b_col = ((lane >> 3) & 1) * 8;

    float acc[2][8][4];
    #pragma unroll
    for (int i = 0; i < 2; i++)
        #pragma unroll
        for (int j = 0; j < 8; j++)
            #pragma unroll
            for (int q = 0; q < 4; q++) acc[i][j][q] = 0.f;

    const uint4* gW = ((const uint4*)&g_wh[0][0][0]) + ((size_t)b * TT + t0) * (SS / 8);
    const uint4* gV = ((const uint4*)&g_vt[0][0][0]) + (size_t)b * EE * (SS / 8);

    int ldr = tid >> 3;          // row 0..31 (x4 iters -> 128)
    int ldc = (tid & 7) * 8;     // k offset in halfs

    for (int k0 = 0; k0 < K; k0 += 64) {
        int k8 = k0 >> 3;
        #pragma unroll
        for (int j = 0; j < 4; j++) {
            int r = ldr + j * 32;
            uint4 wa = gW[(size_t)r * (SS / 8) + k8 + (ldc >> 3)];
            uint4 vb = gV[(size_t)r * (SS / 8) + k8 + (ldc >> 3)];
            *(uint4*)&As[r * LDS_STRIDE + ldc] = wa;
            *(uint4*)&Bs[r * LDS_STRIDE + ldc] = vb;
        }
        __syncthreads();

        #pragma unroll
        for (int ks = 0; ks < 4; ks++) {
            int kk = ks * 16;
            uint32_t afr[2][4];
            #pragma unroll
            for (int mt = 0; mt < 2; mt++) {
                uint32_t addr = as_base +
                    ((a_row + mt * 16) * LDS_STRIDE + kk + a_col) * 2;
                ldm_x4(afr[mt], addr);
            }
            uint32_t bfr[4][4];
            #pragma unroll
            for (int p = 0; p < 4; p++) {
                uint32_t addr = bs_base +
                    ((b_row + p * 16) * LDS_STRIDE + kk + b_col) * 2;
                ldm_x4(bfr[p], addr);
            }
            #pragma unroll
            for (int mt = 0; mt < 2; mt++)
                #pragma unroll
                for (int p = 0; p < 4; p++) {
                    mma16816(acc[mt][2 * p],     afr[mt], bfr[p][0], bfr[p][1]);
                    mma16816(acc[mt][2 * p + 1], afr[mt], bfr[p][2], bfr[p][3]);
                }
        }
        __syncthreads();
    }

    // epilogue: d0,d1 -> (row, col..col+1); d2,d3 -> (row+8, ...)
    int er = t0 + wm * 32 + (lane >> 2);
    int ec = wn * 64 + (lane & 3) * 2;
    #pragma unroll
    for (int mt = 0; mt < 2; mt++) {
        #pragma unroll
        for (int nt = 0; nt < 8; nt++) {
            int row = er + mt * 16;
            int col = ec + nt * 8;
            float* p0 = out + ((size_t)row * BB + b) * EE + col;
            float* p1 = out + ((size_t)(row + 8) * BB + b) * EE + col;
            *(float2*)p0 = make_float2(acc[mt][nt][0], acc[mt][nt][1]);
            *(float2*)p1 = make_float2(acc[mt][nt][2], acc[mt][nt][3]);
        }
    }
}

extern "C" void kernel_launch(void* const* d_in, const int* in_sizes, int n_in,
                              void* d_out, int out_size) {
    const float* v1 = (const float*)d_in[0];
    const float* v2 = (const float*)d_in[1];
    const float* d1 = (const float*)d_in[2];
    const float* d2 = (const float*)d_in[3];
    const float* u  = (const float*)d_in[4];
    float* out = (float*)d_out;

    k_prep<<<BB, TT>>>(d1, d2, u);
    k_m<<<dim3(TT, 16), BB>>>();
    k_w<<<dim3(16, BB), 256>>>();
    k_vt<<<dim3(16, BB), 256>>>(v1, v2);
    k_gemm<<<dim3(4, BB), 256>>>(out);
}

// round 5
// speedup vs baseline: 4.4265x; 1.1972x over previous
#include <cuda_runtime.h>
#include <cuda_fp16.h>
#include <cstdint>

#define TT 512
#define BB 128
#define EE 128
#define SS 1024
#define LOG2T 10

// ---- tables ----
__device__ float g_h[BB][TT + 1];      // g_h[b][0]=0, g_h[b][t+1]=h_t
__device__ float g_e[BB][TT];          // e[tau] = h_{tau-1} - d1_tau
__device__ float g_gtop[BB][TT];       // h_t - u_t
__device__ float g_st[BB][LOG2T][TT];  // sparse table over h (b-major)
__device__ float g_h_tm[TT + 1][BB];   // t-major copies for k_m
__device__ float g_e_tm[TT][BB];
__device__ float g_gtop_tm[TT][BB];
__device__ float g_st_tm[LOG2T][TT][BB];
__device__ float g_m[TT][SS];          // batch-max per (t, slot)
__device__ __half g_wh[BB][TT][SS];    // W as fp16
__device__ __half g_vt[BB][EE][SS];    // V^T as fp16

// ---------------------------------------------------------------------------
// helpers
// ---------------------------------------------------------------------------
__device__ __forceinline__ uint32_t su32(const void* p) {
    uint32_t a;
    asm("{ .reg .u64 t; cvta.to.shared.u64 t, %1; cvt.u32.u64 %0, t; }"
        : "=r"(a) : "l"(p));
    return a;
}
__device__ __forceinline__ void ldm_x4(uint32_t* r, uint32_t addr) {
    asm volatile("ldmatrix.sync.aligned.m8n8.x4.shared.b16 {%0,%1,%2,%3}, [%4];"
                 : "=r"(r[0]), "=r"(r[1]), "=r"(r[2]), "=r"(r[3]) : "r"(addr));
}
__device__ __forceinline__ void mma16816(float* d, const uint32_t* a,
                                         uint32_t b0, uint32_t b1) {
    asm volatile(
        "mma.sync.aligned.m16n8k16.row.col.f32.f16.f16.f32 "
        "{%0,%1,%2,%3}, {%4,%5,%6,%7}, {%8,%9}, {%0,%1,%2,%3};"
        : "+f"(d[0]), "+f"(d[1]), "+f"(d[2]), "+f"(d[3])
        : "r"(a[0]), "r"(a[1]), "r"(a[2]), "r"(a[3]), "r"(b0), "r"(b1));
}
__device__ __forceinline__ void cp16(uint32_t s, const void* g) {
    asm volatile("cp.async.cg.shared.global [%0], [%1], 16;"
                 :: "r"(s), "l"(g) : "memory");
}
__device__ __forceinline__ void cp_commit() {
    asm volatile("cp.async.commit_group;" ::: "memory");
}
__device__ __forceinline__ void cp_wait1() {
    asm volatile("cp.async.wait_group 1;" ::: "memory");
}

// ---------------------------------------------------------------------------
// K1: per-batch fp64 prefix sums + sparse table. One block per batch.
// ---------------------------------------------------------------------------
__global__ void k_prep(const float* __restrict__ d1,
                       const float* __restrict__ d2,
                       const float* __restrict__ uu_) {
    int b = blockIdx.x;
    int t = threadIdx.x;  // 512 threads

    float d1v = d1[t * BB + b];
    float d2v = d2[t * BB + b];
    float uv  = uu_[t * BB + b];
    double P = (double)d1v + (double)d2v;
    double U = (double)uv;

    __shared__ double sP[16], sU[16];
    int lane = t & 31, warp = t >> 5;
    double pi = P, ui = U;
    #pragma unroll
    for (int o = 1; o < 32; o <<= 1) {
        double a = __shfl_up_sync(0xffffffffu, pi, o);
        double c = __shfl_up_sync(0xffffffffu, ui, o);
        if (lane >= o) { pi += a; ui += c; }
    }
    if (lane == 31) { sP[warp] = pi; sU[warp] = ui; }
    __syncthreads();
    if (warp == 0) {
        double pw = (lane < 16) ? sP[lane] : 0.0;
        double uw = (lane < 16) ? sU[lane] : 0.0;
        #pragma unroll
        for (int o = 1; o < 16; o <<= 1) {
            double a = __shfl_up_sync(0xffffffffu, pw, o);
            double c = __shfl_up_sync(0xffffffffu, uw, o);
            if (lane >= o) { pw += a; uw += c; }
        }
        if (lane < 16) { sP[lane] = pw; sU[lane] = uw; }
    }
    __syncthreads();
    double PP = pi + (warp ? sP[warp - 1] : 0.0);
    double UU = ui + (warp ? sU[warp - 1] : 0.0);

    float h    = (float)(UU - PP);
    float ev   = (float)((UU - U) - (PP - P) - (double)d1v);
    float gtop = (float)(UU - PP - (double)uv);

    g_h[b][t + 1]    = h;
    g_h_tm[t + 1][b] = h;
    if (t == 0) { g_h[b][0] = 0.f; g_h_tm[0][b] = 0.f; }
    g_e[b][t]       = ev;
    g_e_tm[t][b]    = ev;
    g_gtop[b][t]    = gtop;
    g_gtop_tm[t][b] = gtop;

    __shared__ float buf0[TT], buf1[TT];
    buf0[t] = h;
    g_st[b][0][t]    = h;
    g_st_tm[0][t][b] = h;
    __syncthreads();
    float* prev = buf0;
    float* cur  = buf1;
    for (int k = 1; k < LOG2T; k++) {
        int off = 1 << (k - 1);
        int j = t + off;
        if (j > TT - 1) j = TT - 1;
        float v = fmaxf(prev[t], prev[j]);
        cur[t] = v;
        g_st[b][k][t]    = v;
        g_st_tm[k][t][b] = v;
        __syncthreads();
        float* tmp = prev; prev = cur; cur = tmp;
    }
}

// ---------------------------------------------------------------------------
// K2: m[t][s] = max_b (u - used). grid (TT, 16), 128 threads (b = tid).
// ---------------------------------------------------------------------------
__global__ void k_m(void) {
    int t = blockIdx.x;
    int tau0 = blockIdx.y * 32;
    if (tau0 > t) return;
    int b = threadIdx.x;
    int lane = b & 31, w = b >> 5;
    float ht = g_h_tm[t + 1][b];

    __shared__ float part[4][64];

    int nt = t - tau0 + 1;
    if (nt > 32) nt = 32;
    for (int i = 0; i < nt; i++) {
        int tau = tau0 + i;
        float G;
        if (tau == t) {
            G = g_gtop_tm[t][b];
        } else {
            int len = t - tau;
            int k = 31 - __clz(len);
            G = fmaxf(g_st_tm[k][tau][b], g_st_tm[k][t - (1 << k)][b]);
        }
        float Bv = fmaxf(g_e_tm[tau][b], G);
        float v1 = ht - Bv;
        float v2 = ht - G;
        #pragma unroll
        for (int o = 16; o; o >>= 1) {
            v1 = fmaxf(v1, __shfl_xor_sync(0xffffffffu, v1, o));
            v2 = fmaxf(v2, __shfl_xor_sync(0xffffffffu, v2, o));
        }
        if (lane == 0) { part[w][2 * i] = v1; part[w][2 * i + 1] = v2; }
    }
    __syncthreads();
    if (b < 2 * nt) {
        float m = fmaxf(fmaxf(part[0][b], part[1][b]),
                        fmaxf(part[2][b], part[3][b]));
        g_m[t][2 * tau0 + b] = m;
    }
}

// ---------------------------------------------------------------------------
// K3: W -> g_wh fp16. Block = (t-chunk of 32, b); tables staged in smem.
// ---------------------------------------------------------------------------
__global__ void __launch_bounds__(256) k_w(void) {
    int tb = blockIdx.x * 32;
    int b  = blockIdx.y;
    int tid = threadIdx.x;

    __shared__ float st_s[LOG2T * TT];
    __shared__ float e_s[TT];
    __shared__ float h_s[TT];
    __shared__ float gt_s[32];

    const float* src = &g_st[b][0][0];
    for (int i = tid; i < LOG2T * TT; i += 256) st_s[i] = src[i];
    for (int i = tid; i < TT; i += 256) { e_s[i] = g_e[b][i]; h_s[i] = g_h[b][i]; }
    if (tid < 32) gt_s[tid] = g_gtop[b][tb + tid];
    __syncthreads();

    int s0 = (tid & 127) * 8;
    for (int tt = 0; tt < 16; tt++) {
        int r = tt * 2 + (tid >> 7);
        int t = tb + r;
        int s_end = ((t >> 7) + 1) << 8;
        if (s0 >= s_end) continue;

        float4 m0 = *(const float4*)&g_m[t][s0];
        float4 m1 = *(const float4*)&g_m[t][s0 + 4];
        float mv[8] = {m0.x, m0.y, m0.z, m0.w, m1.x, m1.y, m1.z, m1.w};

        __align__(16) __half wv[8];
        #pragma unroll
        for (int jj = 0; jj < 4; jj++) {
            int tau = (s0 >> 1) + jj;
            float we = 0.f, wo = 0.f;
            if (tau <= t) {
                float G;
                if (tau == t) {
                    G = gt_s[r];
                } else {
                    int len = t - tau;
                    int k = 31 - __clz(len);
                    G = fmaxf(st_s[k * TT + tau], st_s[k * TT + t - (1 << k)]);
                }
                float Bv = fmaxf(e_s[tau], G);
                we = fminf(fmaxf(h_s[tau], G) - Bv, mv[2 * jj]);
                wo = fminf(Bv - G, mv[2 * jj + 1]);
            }
            wv[2 * jj]     = __float2half(we);
            wv[2 * jj + 1] = __float2half(wo);
        }
        *(uint4*)&g_wh[b][t][s0] = *(const uint4*)wv;
    }
}

// ---------------------------------------------------------------------------
// K4: transpose+convert V -> g_vt[b][e][s] fp16. Block = (s-chunk 64, b).
// float4 loads, half2 smem stores (132-half padded rows).
// ---------------------------------------------------------------------------
__global__ void __launch_bounds__(256) k_vt(const float* __restrict__ v1,
                                            const float* __restrict__ v2) {
    int sc = blockIdx.x;      // 0..15
    int b  = blockIdx.y;
    int tid = threadIdx.x;
    int tau0 = sc * 32;

    __shared__ __half sv[64][132];

    #pragma unroll
    for (int u = tid; u < 2048; u += 256) {
        int sel = u >> 10;            // 0: v1, 1: v2
        int q = u & 1023;
        int i = q >> 5;               // tau index 0..31
        int e4 = (q & 31) * 4;
        const float* src = sel ? v2 : v1;
        float4 f = *(const float4*)(src + ((size_t)(tau0 + i) * BB + b) * EE + e4);
        *(__half2*)&sv[2 * i + sel][e4]     = __floats2half2_rn(f.x, f.y);
        *(__half2*)&sv[2 * i + sel][e4 + 2] = __floats2half2_rn(f.z, f.w);
    }
    __syncthreads();

    int e = tid >> 1, sh = (tid & 1) * 32;
    __align__(16) __half hb[32];
    #pragma unroll
    for (int j = 0; j < 32; j++) hb[j] = sv[sh + j][e];
    uint4* gout = (uint4*)&g_vt[b][e][sc * 64 + sh];
    const uint4* hb4 = (const uint4*)hb;
    gout[0] = hb4[0]; gout[1] = hb4[1]; gout[2] = hb4[2]; gout[3] = hb4[3];
}

// ---------------------------------------------------------------------------
// K5: mma.sync fp16 GEMM, cp.async double-buffered.
// Block: D[128t x 128e] = W[128 x K] @ Vt^T. K chunks of 64.
// 8 warps = 4(m) x 2(n), warp tile 32x64. Heavy blocks (c=3) launch first.
// ---------------------------------------------------------------------------
#define LDS_STRIDE 72                 // halfs per row (144B)
#define TILE_H (128 * LDS_STRIDE)     // halfs per tile
#define STAGE_H (2 * TILE_H)          // halfs per stage (A + B)
#define STAGE_B (STAGE_H * 2)         // bytes per stage: 36864
#define GEMM_SMEM (2 * STAGE_B)       // 73728

__global__ void __launch_bounds__(256, 2) k_gemm(float* __restrict__ out) {
    extern __shared__ __half dynsh[];
    int bid = blockIdx.x;
    int c = 3 - (bid >> 7);
    int b = bid & 127;
    int t0 = c * 128;
    int n = 4 * (c + 1);  // 64-slot chunks

    int tid = threadIdx.x;
    int wid = tid >> 5, lane = tid & 31;
    int wm = wid >> 1, wn = wid & 1;

    uint32_t s_base = su32(dynsh);

    const uint4* gW = ((const uint4*)&g_wh[0][0][0]) + ((size_t)b * TT + t0) * (SS / 8);
    const uint4* gV = ((const uint4*)&g_vt[0][0][0]) + (size_t)b * EE * (SS / 8);

    int ldr = tid >> 3;            // base row 0..31
    int ldc = tid & 7;             // 16B unit within 64-half chunk
    uint32_t sA0 = s_base + (ldr * LDS_STRIDE + ldc * 8) * 2;

    // issue loads for chunk i into stage p
    auto load_chunk = [&](int i, int p) {
        int k8 = i * 8;
        uint32_t sa = sA0 + p * STAGE_B;
        uint32_t sb = sa + TILE_H * 2;
        #pragma unroll
        for (int j = 0; j < 4; j++) {
            int r = ldr + j * 32;
            size_t go = (size_t)r * (SS / 8) + k8 + ldc;
            uint32_t so = j * 32 * LDS_STRIDE * 2;
            cp16(sa + so, gW + go);
            cp16(sb + so, gV + go);
        }
        cp_commit();
    };

    float acc[2][8][4];
    #pragma unroll
    for (int i = 0; i < 2; i++)
        #pragma unroll
        for (int j = 0; j < 8; j++)
            #pragma unroll
            for (int q = 0; q < 4; q++) acc[i][j][q] = 0.f;

    int a_row = wm * 32 + (lane & 15);
    int a_col = (lane >> 4) * 8;
    int b_row = wn * 64 + (lane >> 4) * 8 + (lane & 7);
    int b_col = ((lane >> 3) & 1) * 8;

    load_chunk(0, 0);

    for (int i = 0; i < n; i++) {
        int p = i & 1;
        if (i + 1 < n) load_chunk(i + 1, p ^ 1);
        else cp_commit();  // empty group keeps wait_group 1 correct
        cp_wait1();
        __syncthreads();

        uint32_t as_b = s_base + p * STAGE_B;
        uint32_t bs_b = as_b + TILE_H * 2;

        #pragma unroll
        for (int ks = 0; ks < 4; ks++) {
            int kk = ks * 16;
            uint32_t afr[2][4];
            #pragma unroll
            for (int mt = 0; mt < 2; mt++)
                ldm_x4(afr[mt], as_b + ((a_row + mt * 16) * LDS_STRIDE + kk + a_col) * 2);
            uint32_t bfr[4][4];
            #pragma unroll
            for (int pp = 0; pp < 4; pp++)
                ldm_x4(bfr[pp], bs_b + ((b_row + pp * 16) * LDS_STRIDE + kk + b_col) * 2);
            #pragma unroll
            for (int mt = 0; mt < 2; mt++)
                #pragma unroll
                for (int pp = 0; pp < 4; pp++) {
                    mma16816(acc[mt][2 * pp],     afr[mt], bfr[pp][0], bfr[pp][1]);
                    mma16816(acc[mt][2 * pp + 1], afr[mt], bfr[pp][2], bfr[pp][3]);
                }
        }
        __syncthreads();
    }

    // epilogue
    int er = t0 + wm * 32 + (lane >> 2);
    int ec = wn * 64 + (lane & 3) * 2;
    #pragma unroll
    for (int mt = 0; mt < 2; mt++) {
        #pragma unroll
        for (int nt = 0; nt < 8; nt++) {
            int row = er + mt * 16;
            int col = ec + nt * 8;
            float* p0 = out + ((size_t)row * BB + b) * EE + col;
            float* p1 = out + ((size_t)(row + 8) * BB + b) * EE + col;
            *(float2*)p0 = make_float2(acc[mt][nt][0], acc[mt][nt][1]);
            *(float2*)p1 = make_float2(acc[mt][nt][2], acc[mt][nt][3]);
        }
    }
}

extern "C" void kernel_launch(void* const* d_in, const int* in_sizes, int n_in,
                              void* d_out, int out_size) {
    const float* v1 = (const float*)d_in[0];
    const float* v2 = (const float*)d_in[1];
    const float* d1 = (const float*)d_in[2];
    const float* d2 = (const float*)d_in[3];
    const float* u  = (const float*)d_in[4];
    float* out = (float*)d_out;

    cudaFuncSetAttribute(k_gemm, cudaFuncAttributeMaxDynamicSharedMemorySize, GEMM_SMEM);

    k_prep<<<BB, TT>>>(d1, d2, u);
    k_m<<<dim3(TT, 16), BB>>>();
    k_w<<<dim3(16, BB), 256>>>();
    k_vt<<<dim3(16, BB), 256>>>(v1, v2);
    k_gemm<<<512, 256, GEMM_SMEM>>>(out);
}